// round 10
// baseline (speedup 1.0000x reference)
#include <cuda_runtime.h>

// QuantileLoss: out = mean( concat( (preds[:,:3]-target[:,:3])^2  (3N elems),
//                                   lower (N), lower (N) ) )
// lower = p3>p2 ? 1000 : (p3 > 0.95*t2 ? 0 : (p3-0.95*t2)^2)
// => out = sum_rows( mse_row + 2*lower_row ) / (5*N)
//
// SINGLE kernel, register-disciplined:
//   R9 showed the fused tail inflated regs to 38 -> occ 66.9% -> 5.9 TB/s.
//   Fixes: __launch_bounds__(256, 8) caps regs at 32 (8 CTAs/SM = 100% occ),
//   and the finalize tail is fp32-only (total ~6e7 and 1/(5N) are exact
//   enough in fp32; measured rel_err with fp32 accumulation is ~1e-7).
//   Ordering: relaxed fp32 atomicAdd into g_sum, then atom.release.gpu.inc
//   on g_done (wraps to 0 at NBLOCKS-1 -> self-resetting per graph replay);
//   the last block acquire-reads g_sum, multiplies by 1/(5N), stores, resets.
//   No __threadfence (no CCTL.IVALL), no doubles, no shared broadcast.

#define NROWS 8388608
#define UNITS (NROWS / 4)              // 2^21 four-row units
#define NBLOCKS 4096
#define NTHREADS 256
#define GSTRIDE (NBLOCKS * NTHREADS)   // 2^20 -> exactly 2 units/thread

__device__ float        g_sum  = 0.0f;
__device__ unsigned int g_done = 0u;

__device__ __forceinline__ unsigned int atomic_inc_release(unsigned int* p,
                                                           unsigned int wrap) {
    unsigned int old;
    asm volatile("atom.release.gpu.global.inc.u32 %0, [%1], %2;"
                 : "=r"(old) : "l"(p), "r"(wrap) : "memory");
    return old;
}

__device__ __forceinline__ float atomic_read_acquire(float* p) {
    float old;
    asm volatile("atom.acquire.gpu.global.add.f32 %0, [%1], %2;"
                 : "=f"(old) : "l"(p), "f"(0.0f) : "memory");
    return old;
}

__device__ __forceinline__ float row_loss(float pc0, float pc1, float pc2, float pc3,
                                          float tc0, float tc1, float tc2) {
    float d0 = pc0 - tc0;
    float d1 = pc1 - tc1;
    float d2 = pc2 - tc2;
    float mse = fmaf(d0, d0, fmaf(d1, d1, d2 * d2));
    float q = tc2 * 0.95f;
    float d = pc3 - q;
    float lower = (pc3 > pc2) ? 1000.0f : ((pc3 > q) ? 0.0f : d * d);
    return fmaf(2.0f, lower, mse);
}

__device__ __forceinline__ float unit_loss(const float4* __restrict__ p4,
                                           const float4* __restrict__ t4,
                                           int u) {
    const float4* pb = p4 + (size_t)u * 5;   // 4 rows of preds = 5 aligned float4
    float4 p0 = pb[0];
    float4 p1 = pb[1];
    float4 p2 = pb[2];
    float4 p3 = pb[3];
    float4 p4v = pb[4];
    const float4* tb = t4 + (size_t)u * 3;   // 4 rows of target = 3 aligned float4
    float4 t0 = tb[0];
    float4 t1 = tb[1];
    float4 t2 = tb[2];

    float s = row_loss(p0.x, p0.y, p0.z, p0.w, t0.x, t0.y, t0.z);
    s += row_loss(p1.y, p1.z, p1.w, p2.x, t0.w, t1.x, t1.y);
    s += row_loss(p2.z, p2.w, p3.x, p3.y, t1.z, t1.w, t2.x);
    s += row_loss(p3.w, p4v.x, p4v.y, p4v.z, t2.y, t2.z, t2.w);
    return s;
}

__global__ __launch_bounds__(NTHREADS, 8)   // cap at 32 regs -> 8 CTAs/SM
void ql_kernel(const float4* __restrict__ p4,
               const float4* __restrict__ t4,
               float* __restrict__ out) {
    const int tid = threadIdx.x;
    const int u0 = blockIdx.x * NTHREADS + tid;

    // exactly two units per thread, fully unrolled
    float local = unit_loss(p4, t4, u0)
                + unit_loss(p4, t4, u0 + GSTRIDE);

    // ---- block reduce (fp32) ----
    #pragma unroll
    for (int off = 16; off > 0; off >>= 1)
        local += __shfl_down_sync(0xFFFFFFFFu, local, off);

    __shared__ float warp_sums[NTHREADS / 32];
    const int warp = tid >> 5;
    const int lane = tid & 31;
    if (lane == 0) warp_sums[warp] = local;
    __syncthreads();

    if (tid == 0) {
        float bsum = 0.0f;
        #pragma unroll
        for (int w = 0; w < NTHREADS / 32; w++) bsum += warp_sums[w];

        atomicAdd(&g_sum, bsum);                 // relaxed L2 atomic
        // release-ordered completion count; wraps to 0 at NBLOCKS-1
        unsigned int old = atomic_inc_release(&g_done, NBLOCKS - 1);
        if (old == NBLOCKS - 1) {
            // acquire pairs with every block's release-inc: all adds visible
            float totalf = atomic_read_acquire(&g_sum);
            out[0] = totalf * (1.0f / (5.0f * (float)NROWS));  // const-folded
            atomicExch(&g_sum, 0.0f);            // reset for next replay
        }
    }
}

extern "C" void kernel_launch(void* const* d_in, const int* in_sizes, int n_in,
                              void* d_out, int out_size) {
    const float4* preds  = (const float4*)d_in[0];   // (N,5) f32, rows 20B, base 16B-aligned
    const float4* target = (const float4*)d_in[1];   // (N,3) f32
    float* out = (float*)d_out;
    (void)in_sizes; (void)n_in; (void)out_size;

    ql_kernel<<<NBLOCKS, NTHREADS>>>(preds, target, out);
}

// round 13
// speedup vs baseline: 1.0381x; 1.0381x over previous
#include <cuda_runtime.h>

// QuantileLoss: out = mean( concat( (preds[:,:3]-target[:,:3])^2  (3N elems),
//                                   lower (N), lower (N) ) )
// lower = p3>p2 ? 1000 : (p3 > 0.95*t2 ? 0 : (p3-0.95*t2)^2)
// => out = sum_rows( mse_row + 2*lower_row ) / (5*N)
//
// SINGLE kernel, tail decoupled from hot-path codegen:
//   R9/R10 proved the fused finalize tail costs ~5.5us in the STREAMING
//   phase (register allocation / load-schedule perturbation), cancelling the
//   ~4.9us finalize-launch saving. Fix: the entire finalize lives in a
//   __noinline__ device function. The ABI call means ptxas allocates the
//   callee's registers over the call-site live set (bsum, out) instead of
//   raising the kernel-wide peak -> the hot loop keeps its natural reg count
//   and front-batched MLP=16 LDG.128 schedule.
//   Ordering in the cold path: atomicAdd(g_sum) -> __threadfence ->
//   atomicInc(g_done, wrap NBLOCKS-1). Last block: __threadfence ->
//   volatile read of g_sum -> scale -> store -> atomicExch reset.
//   Counter wrap + exch reset => deterministic across graph replays.
//   The fence's CCTL.IVALL is harmless (read-once streaming data, 4096 execs).

#define NROWS 8388608
#define UNITS (NROWS / 4)              // 2^21 four-row units
#define NBLOCKS 4096
#define NTHREADS 256
#define GSTRIDE (NBLOCKS * NTHREADS)   // 2^20 -> exactly 2 units/thread

__device__ float        g_sum  = 0.0f;
__device__ unsigned int g_done = 0u;

__device__ __noinline__ void finalize_block(float bsum, float* out) {
    atomicAdd(&g_sum, bsum);           // relaxed L2 atomic
    __threadfence();                   // order add before counter (cold path)
    unsigned int old = atomicInc(&g_done, NBLOCKS - 1);  // wraps to 0 on last
    if (old == NBLOCKS - 1) {
        __threadfence();               // pair: all adds visible
        float totalf = *(volatile float*)&g_sum;   // ld.global.cv, bypass L1
        out[0] = totalf * (1.0f / (5.0f * (float)NROWS));  // const-folded
        atomicExch(&g_sum, 0.0f);      // reset for next graph replay
    }
}

__device__ __forceinline__ float row_loss(float pc0, float pc1, float pc2, float pc3,
                                          float tc0, float tc1, float tc2) {
    float d0 = pc0 - tc0;
    float d1 = pc1 - tc1;
    float d2 = pc2 - tc2;
    float mse = fmaf(d0, d0, fmaf(d1, d1, d2 * d2));
    float q = tc2 * 0.95f;
    float d = pc3 - q;
    float lower = (pc3 > pc2) ? 1000.0f : ((pc3 > q) ? 0.0f : d * d);
    return fmaf(2.0f, lower, mse);
}

__device__ __forceinline__ float unit_loss(const float4* __restrict__ p4,
                                           const float4* __restrict__ t4,
                                           int u) {
    const float4* pb = p4 + (size_t)u * 5;   // 4 rows of preds = 5 aligned float4
    float4 p0 = pb[0];
    float4 p1 = pb[1];
    float4 p2 = pb[2];
    float4 p3 = pb[3];
    float4 p4v = pb[4];
    const float4* tb = t4 + (size_t)u * 3;   // 4 rows of target = 3 aligned float4
    float4 t0 = tb[0];
    float4 t1 = tb[1];
    float4 t2 = tb[2];

    float s = row_loss(p0.x, p0.y, p0.z, p0.w, t0.x, t0.y, t0.z);
    s += row_loss(p1.y, p1.z, p1.w, p2.x, t0.w, t1.x, t1.y);
    s += row_loss(p2.z, p2.w, p3.x, p3.y, t1.z, t1.w, t2.x);
    s += row_loss(p3.w, p4v.x, p4v.y, p4v.z, t2.y, t2.z, t2.w);
    return s;
}

__global__ __launch_bounds__(NTHREADS)     // NO min-blocks cap: R10 showed it kills MLP
void ql_kernel(const float4* __restrict__ p4,
               const float4* __restrict__ t4,
               float* __restrict__ out) {
    const int tid = threadIdx.x;
    const int u0 = blockIdx.x * NTHREADS + tid;

    // exactly two units per thread, fully unrolled (16 LDG.128 front-batched)
    float local = unit_loss(p4, t4, u0)
                + unit_loss(p4, t4, u0 + GSTRIDE);

    // ---- block reduce (fp32) ----
    #pragma unroll
    for (int off = 16; off > 0; off >>= 1)
        local += __shfl_down_sync(0xFFFFFFFFu, local, off);

    __shared__ float warp_sums[NTHREADS / 32];
    const int warp = tid >> 5;
    const int lane = tid & 31;
    if (lane == 0) warp_sums[warp] = local;
    __syncthreads();

    if (tid == 0) {
        float bsum = 0.0f;
        #pragma unroll
        for (int w = 0; w < NTHREADS / 32; w++) bsum += warp_sums[w];
        finalize_block(bsum, out);     // cold ABI call: regs charged to callee
    }
}

extern "C" void kernel_launch(void* const* d_in, const int* in_sizes, int n_in,
                              void* d_out, int out_size) {
    const float4* preds  = (const float4*)d_in[0];   // (N,5) f32, rows 20B, base 16B-aligned
    const float4* target = (const float4*)d_in[1];   // (N,3) f32
    float* out = (float*)d_out;
    (void)in_sizes; (void)n_in; (void)out_size;

    ql_kernel<<<NBLOCKS, NTHREADS>>>(preds, target, out);
}

// round 16
// speedup vs baseline: 1.1412x; 1.0993x over previous
#include <cuda_runtime.h>

// QuantileLoss: out = mean( concat( (preds[:,:3]-target[:,:3])^2  (3N elems),
//                                   lower (N), lower (N) ) )
// lower = p3>p2 ? 1000 : (p3 > 0.95*t2 ? 0 : (p3-0.95*t2)^2)
// => out = sum_rows( mse_row + 2*lower_row ) / (5*N)
//
// Two launches (fusion abandoned: 4 variants all cost ~5-6us of streaming
// bandwidth; memcpy-node finalize from R14 suspected of killing the
// container, so reverted to the proven trivial finalize kernel):
//   k1: 8192 blocks x 256 thr, EXACTLY 1 four-row unit per thread
//       (8192*256 = 2^21 = UNITS). 8 live float4 -> low natural regcount,
//       front-batched MLP=8, no spills. Block partial PRE-SCALED by 1/(5N),
//       one fp32 atomicAdd into g_sum -> g_sum ends holding the answer.
//   k2: <<<1,1>>> (measured 3.87us in R6): out = g_sum; g_sum = 0.
//       Kernel-boundary ordering makes the reset replay-deterministic.

#define NROWS 8388608
#define UNITS (NROWS / 4)        // 2^21 four-row units
#define NBLOCKS 8192
#define NTHREADS 256             // 8192 * 256 = 2^21 -> exactly 1 unit/thread
#define INV5N (1.0f / (5.0f * 8388608.0f))

__device__ float g_sum = 0.0f;

__device__ __forceinline__ float row_loss(float pc0, float pc1, float pc2, float pc3,
                                          float tc0, float tc1, float tc2) {
    float d0 = pc0 - tc0;
    float d1 = pc1 - tc1;
    float d2 = pc2 - tc2;
    float mse = fmaf(d0, d0, fmaf(d1, d1, d2 * d2));
    float q = tc2 * 0.95f;
    float d = pc3 - q;
    float lower = (pc3 > pc2) ? 1000.0f : ((pc3 > q) ? 0.0f : d * d);
    return fmaf(2.0f, lower, mse);
}

__global__ __launch_bounds__(NTHREADS)
void ql_partial_kernel(const float4* __restrict__ p4,
                       const float4* __restrict__ t4) {
    const int tid = threadIdx.x;
    const int u = blockIdx.x * NTHREADS + tid;   // one unit per thread

    const float4* pb = p4 + (size_t)u * 5;   // 4 rows of preds = 5 aligned float4
    float4 p0 = pb[0];
    float4 p1 = pb[1];
    float4 p2 = pb[2];
    float4 p3 = pb[3];
    float4 p4v = pb[4];
    const float4* tb = t4 + (size_t)u * 3;   // 4 rows of target = 3 aligned float4
    float4 t0 = tb[0];
    float4 t1 = tb[1];
    float4 t2 = tb[2];

    // row 0: preds {p0.x,p0.y,p0.z,p0.w}    target {t0.x,t0.y,t0.z}
    float local = row_loss(p0.x, p0.y, p0.z, p0.w, t0.x, t0.y, t0.z);
    // row 1: preds {p1.y,p1.z,p1.w,p2.x}    target {t0.w,t1.x,t1.y}
    local += row_loss(p1.y, p1.z, p1.w, p2.x, t0.w, t1.x, t1.y);
    // row 2: preds {p2.z,p2.w,p3.x,p3.y}    target {t1.z,t1.w,t2.x}
    local += row_loss(p2.z, p2.w, p3.x, p3.y, t1.z, t1.w, t2.x);
    // row 3: preds {p3.w,p4v.x,p4v.y,p4v.z} target {t2.y,t2.z,t2.w}
    local += row_loss(p3.w, p4v.x, p4v.y, p4v.z, t2.y, t2.z, t2.w);

    // ---- block reduce (fp32) ----
    #pragma unroll
    for (int off = 16; off > 0; off >>= 1)
        local += __shfl_down_sync(0xFFFFFFFFu, local, off);

    __shared__ float warp_sums[NTHREADS / 32];
    const int warp = tid >> 5;
    const int lane = tid & 31;
    if (lane == 0) warp_sums[warp] = local;
    __syncthreads();

    if (tid == 0) {
        float bsum = 0.0f;
        #pragma unroll
        for (int w = 0; w < NTHREADS / 32; w++) bsum += warp_sums[w];
        // pre-scale so g_sum ends as the final mean; 8192 same-address
        // fp32 atomics spread over block completions: negligible
        atomicAdd(&g_sum, bsum * INV5N);
    }
}

__global__ void ql_final_kernel(float* __restrict__ out) {
    out[0] = g_sum;     // g_sum already holds the mean
    g_sum = 0.0f;       // reset for next graph replay
}

extern "C" void kernel_launch(void* const* d_in, const int* in_sizes, int n_in,
                              void* d_out, int out_size) {
    const float4* preds  = (const float4*)d_in[0];   // (N,5) f32, rows 20B, base 16B-aligned
    const float4* target = (const float4*)d_in[1];   // (N,3) f32
    float* out = (float*)d_out;
    (void)in_sizes; (void)n_in; (void)out_size;

    ql_partial_kernel<<<NBLOCKS, NTHREADS>>>(preds, target);
    ql_final_kernel<<<1, 1>>>(out);
}